// round 16
// baseline (speedup 1.0000x reference)
#include <cuda_runtime.h>

// ------- scratch: 2 x 64MB = 128MB; referenced ONLY from device code ------
static __device__ float bA[16777216];   // z0 | z1 (stage D outputs)
static __device__ float bB[16777216];   // d (stage C output)

// ---------------- filters (scalar + packed-pair tables) -------------------
__constant__ float c_h[9] = {
     0.037828455506995f, -0.02384946501938f, -0.11062440441842f,
     0.37740285561265f,   0.8526986790094f,   0.37740285561265f,
    -0.11062440441842f,  -0.02384946501938f,  0.037828455506995f };
__constant__ float c_g[7] = {
    -0.064538882628938f, -0.040689417609558f, 0.41809227322221f,
     0.78848561640566f,   0.41809227322221f, -0.040689417609558f,
    -0.064538882628938f };
__constant__ float c_f[12] = {
     0.0144f,  0.0272f,  0.0526f,  0.0972f,  0.193f,  0.63f,
    -0.63f,   -0.193f,  -0.0972f, -0.0526f, -0.0272f, -0.0144f };
__constant__ float2 c_h2[9] = {
    {0.037828455506995f,0.037828455506995f}, {-0.02384946501938f,-0.02384946501938f},
    {-0.11062440441842f,-0.11062440441842f}, {0.37740285561265f,0.37740285561265f},
    {0.8526986790094f,0.8526986790094f},     {0.37740285561265f,0.37740285561265f},
    {-0.11062440441842f,-0.11062440441842f}, {-0.02384946501938f,-0.02384946501938f},
    {0.037828455506995f,0.037828455506995f} };
__constant__ float2 c_g2[7] = {
    {-0.064538882628938f,-0.064538882628938f}, {-0.040689417609558f,-0.040689417609558f},
    {0.41809227322221f,0.41809227322221f},     {0.78848561640566f,0.78848561640566f},
    {0.41809227322221f,0.41809227322221f},     {-0.040689417609558f,-0.040689417609558f},
    {-0.064538882628938f,-0.064538882628938f} };
__constant__ float2 c_f2[12] = {
    {0.0144f,0.0144f},  {0.0272f,0.0272f},  {0.0526f,0.0526f},  {0.0972f,0.0972f},
    {0.193f,0.193f},    {0.63f,0.63f},      {-0.63f,-0.63f},    {-0.193f,-0.193f},
    {-0.0972f,-0.0972f},{-0.0526f,-0.0526f},{-0.0272f,-0.0272f},{-0.0144f,-0.0144f} };

#define INV_SQ2 0.7071067811865476f
#define SQ2     1.4142135623730951f
#define SEG     4194304L
#define HM 8388608

__device__ __forceinline__ float2 f2fmap(float2 c, float2 v, float2 a) {
    unsigned long long au = *(unsigned long long*)&a;
    unsigned long long cu = *(unsigned long long*)&c;
    unsigned long long vu = *(unsigned long long*)&v;
    asm("fma.rn.f32x2 %0, %1, %2, %0;" : "+l"(au) : "l"(cu), "l"(vu));
    float2 r; *(unsigned long long*)&r = au; return r;
}
__device__ __forceinline__ float4 f4fmap(float2 c, float4 v, float4 a) {
    float2 lo = f2fmap(c, make_float2(v.x, v.y), make_float2(a.x, a.y));
    float2 hi = f2fmap(c, make_float2(v.z, v.w), make_float2(a.z, a.w));
    return make_float4(lo.x, lo.y, hi.x, hi.y);
}

// ===== K_AB: fused vh(stride2) + hh(stride2). x -> out seg0 (c) ===========
__global__ void __launch_bounds__(256) k_AB(const float* __restrict__ x,
                                            float* __restrict__ outc) {
    __shared__ float4 t[2048];
    int rb = blockIdx.x & 3, img = blockIdx.x >> 2;
    int tid = threadIdx.x;
    const float4* xi = (const float4*)x + ((long)img << 14);
    {
        int jb = tid & 63, ib = tid >> 6;
        for (int rr = ib; rr < 32; rr += 4) {
            int i2 = rb * 32 + rr;
            float4 s = {0.f, 0.f, 0.f, 0.f};
#pragma unroll
            for (int k = 0; k < 9; ++k)
                s = f4fmap(c_h2[k], xi[(((2 * i2 + k - 4) & 255) << 6) + jb], s);
            t[rr * 64 + jb] = s;
        }
    }
    __syncthreads();
    {
        int jb = tid & 31, ib = tid >> 5;
        for (int rr = ib; rr < 32; rr += 8) {
            const float4* trow = t + rr * 64;
            float o0 = 0.f, o1 = 0.f, o2 = 0.f, o3 = 0.f;
#pragma unroll
            for (int s = 0; s < 5; ++s) {
                float4 v = trow[(2 * jb - 2 + s + 64) & 63];
                float vv[4] = {v.x, v.y, v.z, v.w};
#pragma unroll
                for (int u = 0; u < 4; ++u) {
                    int q = 4 * s + u;
                    int k0 = q - 4;  if (k0 >= 0 && k0 < 9) o0 = fmaf(c_h[k0], vv[u], o0);
                    int k1 = q - 6;  if (k1 >= 0 && k1 < 9) o1 = fmaf(c_h[k1], vv[u], o1);
                    int k2 = q - 8;  if (k2 >= 0 && k2 < 9) o2 = fmaf(c_h[k2], vv[u], o2);
                    int k3 = q - 10; if (k3 >= 0 && k3 < 9) o3 = fmaf(c_h[k3], vv[u], o3);
                }
            }
            int i = rb * 32 + rr;
            ((float4*)outc)[((long)img << 12) + (i << 5) + jb] =
                make_float4(o0, o1, o2, o3);
        }
    }
}

// ===== K_C: fused (upsample+vert g) + (horiz g + sub). c,x -> bB = d ======
__global__ void __launch_bounds__(256) k_C(const float* __restrict__ cc,
                                           const float* __restrict__ x) {
    __shared__ float v[4096];
    int rb = blockIdx.x & 7, img = blockIdx.x >> 3;
    int tid = threadIdx.x;
    const float4* ci = (const float4*)cc + ((long)img << 12);
    {
        int jb = tid & 31, ib = tid >> 5;
        for (int rr = ib; rr < 32; rr += 8) {
            int i = rb * 32 + rr;
            float4 s = {0.f, 0.f, 0.f, 0.f};
            if (i & 1) {
#pragma unroll
                for (int k = 0; k < 7; k += 2)
                    s = f4fmap(c_g2[k], ci[((((i + k - 3) & 255) >> 1) << 5) + jb], s);
            } else {
#pragma unroll
                for (int k = 1; k < 7; k += 2)
                    s = f4fmap(c_g2[k], ci[((((i + k - 3) & 255) >> 1) << 5) + jb], s);
            }
            ((float4*)v)[rr * 32 + jb] = s;
        }
    }
    __syncthreads();
    {
        int jb = tid & 63, ib = tid >> 6;
        for (int rr = ib; rr < 32; rr += 4) {
            int i = rb * 32 + rr;
            const float* vr = v + rr * 128;
            float o[4];
#pragma unroll
            for (int m = 0; m < 4; ++m) {
                int j = 4 * jb + m;
                float s = 0.f;
                if (m & 1) {
#pragma unroll
                    for (int k = 0; k < 7; k += 2)
                        s = fmaf(c_g[k], vr[((j + k - 3) & 255) >> 1], s);
                } else {
#pragma unroll
                    for (int k = 1; k < 7; k += 2)
                        s = fmaf(c_g[k], vr[((j + k - 3) & 255) >> 1], s);
                }
                o[m] = s;
            }
            long fi = ((long)img << 14) + (i << 6) + jb;
            float4 xv = ((const float4*)x)[fi];
            ((float4*)bB)[fi] =
                make_float4(xv.x - o[0], xv.y - o[1], xv.z - o[2], xv.w - o[3]);
        }
    }
}

// ===== K_D6: diamond-band gather from d + vert f(qper, OFF=6) + horiz f
//  + y0 combine -> z0 (bA[0..HM)). 8-row tiles, grid = 256 img x 16 rb =====
// p1[v,j]=d[(v-j)&255,(v+j+1)&255] for ALL v (qper_col transparent in d).
// Band per d-row u: contiguous cols from base_u=((2*r0-12-u)&255)&~1, 40 fl.
__global__ void __launch_bounds__(256) k_D6() {
    __shared__ float smd[256 * 39];      // 39936 B
    __shared__ float t[8 * 256];         // 8192 B
    int rb = blockIdx.x & 15, img = blockIdx.x >> 4;
    int r0 = rb << 3;
    int tid = threadIdx.x;
    const float* dimg = bB + ((long)img << 16);
    // loader: 256 d-rows x 20 float2 (40 cols)
    {
        int lane = tid & 7, urow = tid >> 3;
        for (int pass = 0; pass < 8; ++pass) {
            int u = (pass << 5) + urow;
            int base_u = ((2 * r0 - 12 - u) & 255) & ~1;
            const float2* drow = (const float2*)(dimg + (u << 8));
#pragma unroll
            for (int it = 0; it < 3; ++it) {
                int k = lane + (it << 3);
                if (k < 20) {
                    int col = (base_u + 2 * k) & 255;
                    float2 vv = drow[col >> 1];
                    smd[u * 39 + 2 * k]     = vv.x;
                    smd[u * 39 + 2 * k + 1] = vv.y;
                }
            }
        }
    }
    __syncthreads();
    // phase1: vertical 12-tap f over virtual p1 rows; 2 strips x 4 rows
    {
        int j2 = tid & 127, strip = tid >> 7;
        int r0s = r0 + (strip << 2);
        int j0 = 2 * j2, j1 = 2 * j2 + 1;
        float2 acc[4];
#pragma unroll
        for (int q = 0; q < 4; ++q) acc[q] = make_float2(0.f, 0.f);
#pragma unroll
        for (int s = 0; s < 15; ++s) {
            int v = r0s - 6 + s;
            int u0 = (v - j0) & 255;
            int u1 = (v - j1) & 255;
            int ib = 2 * (v - r0) + 13;
            float xx = smd[u0 * 39 + ib + (u0 & 1)];
            float yy = smd[u1 * 39 + ib + (u1 & 1)];
            float2 val = make_float2(xx, yy);
#pragma unroll
            for (int q = 0; q < 4; ++q) {
                int k = s - q;
                if (k >= 0 && k < 12) acc[q] = f2fmap(c_f2[k], val, acc[q]);
            }
        }
#pragma unroll
        for (int q = 0; q < 4; ++q)
            ((float2*)t)[(strip * 4 + q) * 128 + j2] = acc[q];
    }
    __syncthreads();
    // phase2: streamed horiz f (OFF=6) + y0 combine (p0 from smd) -> z0
    {
        int jb = tid & 63, ib2 = tid >> 6;
        for (int rr = ib2; rr < 8; rr += 4) {
            const float4* trow = (const float4*)t + rr * 64;
            float o0 = 0.f, o1 = 0.f, o2 = 0.f, o3 = 0.f;
#pragma unroll
            for (int s = 0; s < 5; ++s) {
                float4 v = trow[(jb - 2 + s + 64) & 63];
                float vv[4] = {v.x, v.y, v.z, v.w};
#pragma unroll
                for (int u = 0; u < 4; ++u) {
                    int q = 4 * s + u;
                    int k0 = q - 2;  if (k0 >= 0 && k0 < 12) o0 = fmaf(c_f[k0], vv[u], o0);
                    int k1 = q - 3;  if (k1 >= 0 && k1 < 12) o1 = fmaf(c_f[k1], vv[u], o1);
                    int k2 = q - 4;  if (k2 >= 0 && k2 < 12) o2 = fmaf(c_f[k2], vv[u], o2);
                    int k3 = q - 5;  if (k3 >= 0 && k3 < 12) o3 = fmaf(c_f[k3], vv[u], o3);
                }
            }
            int i = r0 + rr;
            float p[4];
#pragma unroll
            for (int m = 0; m < 4; ++m) {
                int u = (i - 4 * jb - m) & 255;
                p[m] = smd[u * 39 + 2 * rr + 12 + (u & 1)];
            }
            long fi = ((long)img << 13) + (i << 6) + jb;
            ((float4*)bA)[fi] = make_float4((p[0] - o0) * INV_SQ2,
                                            (p[1] - o1) * INV_SQ2,
                                            (p[2] - o2) * INV_SQ2,
                                            (p[3] - o3) * INV_SQ2);
        }
    }
}

// ===== K_D5: vert f(qper, OFF=5) over z0 + horiz f + y1 combine (p1
//  gathered from d) -> z1 (bA[HM..)). 16-row tiles, grid 2048 ==============
__global__ void __launch_bounds__(256) k_D5() {
    __shared__ float smd2[256 * 17];     // 17408 B  (p1 rows [r0,r0+16))
    __shared__ float t[16 * 256];        // 16384 B
    int rb = blockIdx.x & 7, img = blockIdx.x >> 3;
    int r0 = rb << 4;
    int tid = threadIdx.x;
    const float* dimg = bB + ((long)img << 16);
    // loader: p1[i,j]=d[(i-j)&255,(i+j+1)&255]; per u entry k: i=r0+k
    {
        int lane = tid & 7, urow = tid >> 3;
        for (int pass = 0; pass < 8; ++pass) {
            int u = (pass << 5) + urow;
            const float2* drow = (const float2*)(dimg + (u << 8));
#pragma unroll
            for (int it = 0; it < 2; ++it) {
                int k = lane + (it << 3);
                int c = (2 * (r0 + k) + 1 - u) & 255;
                float2 vv = drow[c >> 1];
                smd2[u * 17 + k] = (c & 1) ? vv.y : vv.x;
            }
        }
    }
    // phase1: vert f OFF=5 over z0 (coalesced from bA), qper wrap
    {
        const float2* s2 = (const float2*)((const float4*)bA + ((long)img << 13));
        int j2 = tid & 127, strip = tid >> 7;
        int r0s = r0 + (strip << 3);
        float2 acc[8];
#pragma unroll
        for (int q = 0; q < 8; ++q) acc[q] = make_float2(0.f, 0.f);
#pragma unroll
        for (int s = 0; s < 19; ++s) {
            int a = r0s - 5 + s;
            int row = a, c2 = j2;
            if (a < 0)        { row = a + 128; c2 = (j2 + 64) & 127; }
            else if (a > 127) { row = a - 128; c2 = (j2 + 64) & 127; }
            float2 v = s2[(row << 7) + c2];
#pragma unroll
            for (int q = 0; q < 8; ++q) {
                int k = s - q;
                if (k >= 0 && k < 12) acc[q] = f2fmap(c_f2[k], v, acc[q]);
            }
        }
        __syncthreads();
#pragma unroll
        for (int q = 0; q < 8; ++q)
            ((float2*)t)[(strip * 8 + q) * 128 + j2] = acc[q];
    }
    __syncthreads();
    // phase2: streamed horiz f (OFF=5) + y1 combine (p1 from smd2) -> z1
    {
        int jb = tid & 63, ib2 = tid >> 6;
        for (int rr = ib2; rr < 16; rr += 4) {
            const float4* trow = (const float4*)t + rr * 64;
            float o0 = 0.f, o1 = 0.f, o2 = 0.f, o3 = 0.f;
#pragma unroll
            for (int s = 0; s < 5; ++s) {
                float4 v = trow[(jb - 2 + s + 64) & 63];
                float vv[4] = {v.x, v.y, v.z, v.w};
#pragma unroll
                for (int u = 0; u < 4; ++u) {
                    int q = 4 * s + u;
                    int k0 = q - 3;  if (k0 >= 0 && k0 < 12) o0 = fmaf(c_f[k0], vv[u], o0);
                    int k1 = q - 4;  if (k1 >= 0 && k1 < 12) o1 = fmaf(c_f[k1], vv[u], o1);
                    int k2 = q - 5;  if (k2 >= 0 && k2 < 12) o2 = fmaf(c_f[k2], vv[u], o2);
                    int k3 = q - 6;  if (k3 >= 0 && k3 < 12) o3 = fmaf(c_f[k3], vv[u], o3);
                }
            }
            int i = r0 + rr;
            float p[4];
#pragma unroll
            for (int m = 0; m < 4; ++m) {
                int u = (i - 4 * jb - m) & 255;
                p[m] = smd2[u * 17 + rr];
            }
            long fi = ((long)img << 13) + (i << 6) + jb;
            ((float4*)(bA + HM))[fi] = make_float4(-SQ2 * p[0] - o0,
                                                   -SQ2 * p[1] - o1,
                                                   -SQ2 * p[2] - o2,
                                                   -SQ2 * p[3] - o3);
        }
    }
}

// ===== K_E6: diamond-band gather from z + vert f(per, OFF=6) + horiz f
//  + e0 combine -> out segs2/3. 16-row tiles, grid = 512 img x 8 rb ========
// p0b[i,j]=z[(i+j)&127,(zu-2i)&255]; p1b[v,j]=z[(v+j+1)&127,(zu-1-2v)&255].
__global__ void __launch_bounds__(256) k_E6(float* __restrict__ out) {
    __shared__ float smz[128 * 55];      // 28160 B
    __shared__ float t[16 * 128];        // 8192 B
    int rb = blockIdx.x & 7, img = blockIdx.x >> 3;
    int r0 = rb << 4;
    int tid = threadIdx.x;
    int b = img >> 7, ch = img & 127;
    const float* zi = (ch < 64)
        ? (bA      + ((long)((b << 6) + ch)      << 15))
        : (bA + HM + ((long)((b << 6) + ch - 64) << 15));
    // loader: 128 z-rows x 27 float2 (54 cols from base3)
    {
        int lane = tid & 7, urow = tid >> 3;
        for (int pass = 0; pass < 4; ++pass) {
            int zu = (pass << 5) + urow;
            int base3 = ((zu - 2 * r0 - 41) & 255) & ~1;
            const float2* zr = (const float2*)(zi + (zu << 8));
#pragma unroll
            for (int it = 0; it < 4; ++it) {
                int k = lane + (it << 3);
                if (k < 27) {
                    int col = (base3 + 2 * k) & 255;
                    float2 vv = zr[col >> 1];
                    smz[zu * 55 + 2 * k]     = vv.x;
                    smz[zu * 55 + 2 * k + 1] = vv.y;
                }
            }
        }
    }
    __syncthreads();
    // phase1: vert f over p1b; 4 strips x 4 rows
    {
        int j2 = tid & 63, strip = tid >> 6;
        int r0s = r0 + (strip << 2);
        int j0 = 2 * j2, j1 = 2 * j2 + 1;
        float2 acc[4];
#pragma unroll
        for (int q = 0; q < 4; ++q) acc[q] = make_float2(0.f, 0.f);
#pragma unroll
        for (int s = 0; s < 15; ++s) {
            int v = r0s - 6 + s;
            int zu0 = (v + j0 + 1 + 128) & 127;
            int zu1 = (v + j1 + 1 + 128) & 127;
            int ib = 2 * (r0 - v) + 40;
            float xx = smz[zu0 * 55 + ib + ((zu0 + 1) & 1)];
            float yy = smz[zu1 * 55 + ib + ((zu1 + 1) & 1)];
            float2 val = make_float2(xx, yy);
#pragma unroll
            for (int q = 0; q < 4; ++q) {
                int k = s - q;
                if (k >= 0 && k < 12) acc[q] = f2fmap(c_f2[k], val, acc[q]);
            }
        }
#pragma unroll
        for (int q = 0; q < 4; ++q)
            ((float2*)t)[(strip * 4 + q) * 64 + j2] = acc[q];
    }
    __syncthreads();
    // phase2: streamed horiz f (OFF=6) + e0 combine (p0b from smz)
    {
        int jb = tid & 31, ib2 = tid >> 5;
        for (int rr = ib2; rr < 16; rr += 8) {
            const float4* trow = (const float4*)t + rr * 32;
            float o0 = 0.f, o1 = 0.f, o2 = 0.f, o3 = 0.f;
#pragma unroll
            for (int s = 0; s < 5; ++s) {
                float4 v = trow[(jb - 2 + s + 32) & 31];
                float vv[4] = {v.x, v.y, v.z, v.w};
#pragma unroll
                for (int u = 0; u < 4; ++u) {
                    int q = 4 * s + u;
                    int k0 = q - 2;  if (k0 >= 0 && k0 < 12) o0 = fmaf(c_f[k0], vv[u], o0);
                    int k1 = q - 3;  if (k1 >= 0 && k1 < 12) o1 = fmaf(c_f[k1], vv[u], o1);
                    int k2 = q - 4;  if (k2 >= 0 && k2 < 12) o2 = fmaf(c_f[k2], vv[u], o2);
                    int k3 = q - 5;  if (k3 >= 0 && k3 < 12) o3 = fmaf(c_f[k3], vv[u], o3);
                }
            }
            int i = r0 + rr;
            float p[4];
#pragma unroll
            for (int m = 0; m < 4; ++m) {
                int zu = (i + 4 * jb + m) & 127;
                p[m] = smz[zu * 55 + 2 * (r0 - i) + 41 + ((zu + 1) & 1)];
            }
            long base4 = (ch < 64)
                ? (2L * (SEG / 4) + ((long)((b << 6) + ch)      << 12))
                : (3L * (SEG / 4) + ((long)((b << 6) + ch - 64) << 12));
            ((float4*)out)[base4 + (i << 5) + jb] =
                make_float4((p[0] - o0) * INV_SQ2, (p[1] - o1) * INV_SQ2,
                            (p[2] - o2) * INV_SQ2, (p[3] - o3) * INV_SQ2);
        }
    }
}

// ===== K_E5: vert f(per, OFF=5) over e0(out) + horiz f + e1 combine (p1b
//  gathered from z) -> out segs1/4. 32-row tiles, grid 2048 ================
__global__ void __launch_bounds__(256) k_E5(float* __restrict__ out) {
    __shared__ float smz2[128 * 33];     // 16896 B
    __shared__ float t[32 * 128];        // 16384 B
    int rb = blockIdx.x & 3, img = blockIdx.x >> 2;
    int r0 = rb << 5;
    int tid = threadIdx.x;
    int b = img >> 7, ch = img & 127;
    const float* zi = (ch < 64)
        ? (bA      + ((long)((b << 6) + ch)      << 15))
        : (bA + HM + ((long)((b << 6) + ch - 64) << 15));
    // loader: p1b[i,j]=z[zu][(zu-1-2i)&255]; per zu entry k: i=r0+k
    {
        int lane = tid & 7, urow = tid >> 3;
        for (int pass = 0; pass < 4; ++pass) {
            int zu = (pass << 5) + urow;
            const float2* zr = (const float2*)(zi + (zu << 8));
#pragma unroll
            for (int it = 0; it < 4; ++it) {
                int k = lane + (it << 3);
                int c = (zu - 1 - 2 * (r0 + k)) & 255;
                float2 vv = zr[c >> 1];
                smz2[zu * 33 + k] = (c & 1) ? vv.y : vv.x;
            }
        }
    }
    // phase1: vert f OFF=5 over e0 (read from out, coalesced)
    {
        long base4 = (ch < 64)
            ? (2L * (SEG / 4) + ((long)((b << 6) + ch)      << 12))
            : (3L * (SEG / 4) + ((long)((b << 6) + ch - 64) << 12));
        const float2* s2 = (const float2*)((const float4*)out + base4);
        int j2 = tid & 63, strip = tid >> 6;
        int r0s = r0 + (strip << 3);
        float2 acc[8];
#pragma unroll
        for (int q = 0; q < 8; ++q) acc[q] = make_float2(0.f, 0.f);
#pragma unroll
        for (int s = 0; s < 19; ++s) {
            int row = (r0s - 5 + s + 128) & 127;
            float2 v = s2[(row << 6) + j2];
#pragma unroll
            for (int q = 0; q < 8; ++q) {
                int k = s - q;
                if (k >= 0 && k < 12) acc[q] = f2fmap(c_f2[k], v, acc[q]);
            }
        }
        __syncthreads();
#pragma unroll
        for (int q = 0; q < 8; ++q)
            ((float2*)t)[(strip * 8 + q) * 64 + j2] = acc[q];
    }
    __syncthreads();
    // phase2: streamed horiz f (OFF=5) + e1 combine (p1b from smz2)
    {
        int jb = tid & 31, ib2 = tid >> 5;
        for (int rr = ib2; rr < 32; rr += 8) {
            const float4* trow = (const float4*)t + rr * 32;
            float o0 = 0.f, o1 = 0.f, o2 = 0.f, o3 = 0.f;
#pragma unroll
            for (int s = 0; s < 5; ++s) {
                float4 v = trow[(jb - 2 + s + 32) & 31];
                float vv[4] = {v.x, v.y, v.z, v.w};
#pragma unroll
                for (int u = 0; u < 4; ++u) {
                    int q = 4 * s + u;
                    int k0 = q - 3;  if (k0 >= 0 && k0 < 12) o0 = fmaf(c_f[k0], vv[u], o0);
                    int k1 = q - 4;  if (k1 >= 0 && k1 < 12) o1 = fmaf(c_f[k1], vv[u], o1);
                    int k2 = q - 5;  if (k2 >= 0 && k2 < 12) o2 = fmaf(c_f[k2], vv[u], o2);
                    int k3 = q - 6;  if (k3 >= 0 && k3 < 12) o3 = fmaf(c_f[k3], vv[u], o3);
                }
            }
            int i = r0 + rr;
            float p[4];
#pragma unroll
            for (int m = 0; m < 4; ++m) {
                int zu = (i + 4 * jb + m + 1) & 127;
                p[m] = smz2[zu * 33 + rr];
            }
            long base4 = (ch < 64)
                ? (1L * (SEG / 4) + ((long)((b << 6) + ch)      << 12))
                : (4L * (SEG / 4) + ((long)((b << 6) + ch - 64) << 12));
            ((float4*)out)[base4 + (i << 5) + jb] =
                make_float4(-SQ2 * p[0] - o0, -SQ2 * p[1] - o1,
                            -SQ2 * p[2] - o2, -SQ2 * p[3] - o3);
        }
    }
}

extern "C" void kernel_launch(void* const* d_in, const int* in_sizes, int n_in,
                              void* d_out, int out_size) {
    const float* x = (const float*)d_in[0];
    float* out = (float*)d_out;
    (void)in_sizes; (void)n_in; (void)out_size;

    const int T = 256;
    k_AB<<<1024, T>>>(x, out);        // c -> seg0
    k_C<<<2048, T>>>(out, x);         // d -> bB
    k_D6<<<4096, T>>>();              // y0a -> bA[0..HM)   (quincunx fused)
    k_D5<<<2048, T>>>();              // y1a -> bA[HM..)
    k_E6<<<4096, T>>>(out);           // e0 -> segs2/3      (quincunx fused)
    k_E5<<<2048, T>>>(out);           // e1 -> segs1/4
}